// round 4
// baseline (speedup 1.0000x reference)
#include <cuda_runtime.h>
#include <math.h>

#define B_  8
#define C_  64
#define H_  48
#define W_  48
#define S_  2304
#define NH_ 4
#define EPS_ 1.1920929e-07f

typedef unsigned long long ull;

#define FFMA2(acc, av, bv) asm("fma.rn.f32x2 %0, %1, %2, %0;" : "+l"(acc) : "l"(av), "l"(bv))

__device__ __forceinline__ float hsum2(ull v) {
    float lo, hi;
    asm("mov.b64 {%0, %1}, %2;" : "=f"(lo), "=f"(hi) : "l"(v));
    return lo + hi;
}

// ---------------- scratch ----------------------------------------------------
__device__ __align__(16) float g_wT[C_*9*C_];     // conv weights [ci*9+k][co]
__device__ __align__(16) float g_qc[B_*S_*C_];    // conv output   [b][p][c]
__device__ __align__(16) float g_qp[B_*S_*C_];    // proj q        [b][p][e]
__device__ __align__(16) float g_kp[B_*S_*C_];    // proj k        [b][p][e]
__device__ float g_l[B_*S_*NH_];                  // softmax denom [b][i][h]

// ---------------- weight transpose ------------------------------------------
__global__ void wt_kernel(const float* __restrict__ w) {
    int idx = blockIdx.x * 256 + threadIdx.x;
    if (idx >= C_*9*C_) return;
    int co = idx & 63;
    int rk = idx >> 6;
    g_wT[idx] = w[co*(C_*9) + rk];
}

// ---------------- conv 3x3 SAME, writes [b][p][c] ---------------------------
__global__ void __launch_bounds__(256) conv_kernel(const float* __restrict__ q) {
    int b = blockIdx.x / H_;
    int h = blockIdx.x % H_;
    __shared__ float in_s[3][C_][W_];
    const float* qb = q + (size_t)b*C_*H_*W_;
    for (int fl = threadIdx.x; fl < 3*C_*W_; fl += 256) {
        int r = fl / (C_*W_);
        int c = (fl / W_) % C_;
        int w = fl % W_;
        int hy = h + r - 1;
        in_s[r][c][w] = (hy >= 0 && hy < H_) ? qb[c*H_*W_ + hy*W_ + w] : 0.f;
    }
    __syncthreads();

    int co   = threadIdx.x & 63;
    int wg   = threadIdx.x >> 6;
    int base = wg * 12;

    float acc[12];
#pragma unroll
    for (int u = 0; u < 12; u++) acc[u] = 0.f;

    for (int ci = 0; ci < C_; ci++) {
#pragma unroll
        for (int r = 0; r < 3; r++) {
            float xi[14];
#pragma unroll
            for (int u = 0; u < 14; u++) {
                int x = base - 1 + u;
                xi[u] = (x >= 0 && x < W_) ? in_s[r][ci][x] : 0.f;
            }
            const float* wrow = &g_wT[(ci*9 + r*3)*C_ + co];
#pragma unroll
            for (int kw = 0; kw < 3; kw++) {
                float wv = wrow[kw*C_];
#pragma unroll
                for (int ww = 0; ww < 12; ww++) acc[ww] += xi[ww + kw] * wv;
            }
        }
    }
    float* outp = g_qc + ((size_t)b*S_ + h*W_ + base)*C_ + co;
#pragma unroll
    for (int ww = 0; ww < 12; ww++) outp[ww*C_] = acc[ww];
}

// ---------------- rmsnorm + projection, f32x2, writes [b][p][e] -------------
template <bool IS_Q>
__global__ void __launch_bounds__(256) normproj_kernel(
        const float* __restrict__ xin,
        const float* __restrict__ wmat,
        const float* __restrict__ nw,
        const float* __restrict__ bias,
        float scale)
{
    int b  = blockIdx.y;
    int p0 = blockIdx.x * 32;
    __shared__ __align__(16) float wm[64*68];
    __shared__ __align__(16) float xs[32*68];
    __shared__ float rinv[32];
    __shared__ float bs[64];
    int tid = threadIdx.x;

    for (int fl = tid; fl < 4096; fl += 256) {
        int e = fl >> 6, c = fl & 63;
        wm[e*68 + c] = wmat[fl] * nw[c];
    }
    if (tid < 64) bs[tid] = bias[tid];

    if (IS_Q) {
        const float4* src = (const float4*)(g_qc + ((size_t)b*S_ + p0)*C_);
        for (int fl = tid; fl < 512; fl += 256) {
            int i = fl >> 4, c4 = fl & 15;
            float4 v = src[i*16 + c4];
            float* d = &xs[i*68 + c4*4];
            d[0] = v.x; d[1] = v.y; d[2] = v.z; d[3] = v.w;
        }
    } else {
        const float* src = xin + (size_t)b*C_*S_ + p0;
        for (int fl = tid; fl < 2048; fl += 256) {
            int c = fl >> 5, i = fl & 31;
            xs[i*68 + c] = src[c*S_ + i];
        }
    }
    __syncthreads();

    {   // sum of squares per position
        int i = tid >> 3, sub = tid & 7;
        float ss = 0.f;
#pragma unroll
        for (int u = 0; u < 8; u++) { float v = xs[i*68 + sub*8 + u]; ss += v*v; }
#pragma unroll
        for (int m = 4; m >= 1; m >>= 1) ss += __shfl_xor_sync(0xffffffffu, ss, m);
        if (sub == 0) rinv[i] = rsqrtf(ss * (1.f/64.f) + EPS_);
    }
    __syncthreads();

    int e  = tid & 63;
    int ig = tid >> 6;   // 0..3 -> i = rep*4+ig, 8 reps
    ull acca[8], accb[8];
#pragma unroll
    for (int r = 0; r < 8; r++) { acca[r] = 0ULL; accb[r] = 0ULL; }

#pragma unroll
    for (int c = 0; c < 64; c += 4) {
        ulonglong2 w2 = *(const ulonglong2*)&wm[e*68 + c];
#pragma unroll
        for (int r = 0; r < 8; r++) {
            int i = r*4 + ig;
            ulonglong2 x2 = *(const ulonglong2*)&xs[i*68 + c];
            FFMA2(acca[r], x2.x, w2.x);
            FFMA2(accb[r], x2.y, w2.y);
        }
    }

    float* dst = (IS_Q ? g_qp : g_kp) + ((size_t)b*S_ + p0)*C_ + e;
#pragma unroll
    for (int r = 0; r < 8; r++) {
        int i = r*4 + ig;
        float acc = hsum2(acca[r]) + hsum2(accb[r]);
        dst[(size_t)i*C_] = (acc * rinv[i] + bs[e]) * scale;
    }
}

// ---------------- pass 1: per-head softmax denominators ---------------------
__global__ void __launch_bounds__(256) attn_l_kernel() {
    int b  = blockIdx.y;
    int i0 = blockIdx.x * 64;
    __shared__ __align__(16) float qs[64*68];   // [i][c]
    __shared__ __align__(16) float ks[64*68];   // [j][c]
    int tid = threadIdx.x;
    int tx = tid & 15, ty = tid >> 4;

    for (int fl = tid; fl < 4096; fl += 256) {
        int i = fl >> 6, c = fl & 63;
        qs[i*68 + c] = g_qp[((size_t)b*S_ + i0 + i)*C_ + c];
    }

    float lacc[4][4];
#pragma unroll
    for (int a = 0; a < 4; a++)
#pragma unroll
        for (int h = 0; h < 4; h++) lacc[a][h] = 0.f;

    for (int kt = 0; kt < S_/64; kt++) {
        __syncthreads();
        for (int fl = tid; fl < 4096; fl += 256) {
            int j = fl >> 6, c = fl & 63;
            ks[j*68 + c] = g_kp[((size_t)b*S_ + kt*64 + j)*C_ + c];
        }
        __syncthreads();
#pragma unroll
        for (int h = 0; h < 4; h++) {
            ull s2[4][4];
#pragma unroll
            for (int a = 0; a < 4; a++)
#pragma unroll
                for (int bb = 0; bb < 4; bb++) s2[a][bb] = 0ULL;
#pragma unroll
            for (int q4 = 0; q4 < 4; q4++) {
                int c = h*16 + q4*4;
                ulonglong2 qa[4], kb[4];
#pragma unroll
                for (int a = 0; a < 4; a++)
                    qa[a] = *(const ulonglong2*)&qs[(4*ty + a)*68 + c];
#pragma unroll
                for (int bb = 0; bb < 4; bb++)
                    kb[bb] = *(const ulonglong2*)&ks[(tx + 16*bb)*68 + c];
#pragma unroll
                for (int a = 0; a < 4; a++)
#pragma unroll
                    for (int bb = 0; bb < 4; bb++) {
                        FFMA2(s2[a][bb], qa[a].x, kb[bb].x);
                        FFMA2(s2[a][bb], qa[a].y, kb[bb].y);
                    }
            }
#pragma unroll
            for (int a = 0; a < 4; a++)
#pragma unroll
                for (int bb = 0; bb < 4; bb++)
                    lacc[a][h] += __expf(hsum2(s2[a][bb]));
        }
    }
#pragma unroll
    for (int a = 0; a < 4; a++)
#pragma unroll
        for (int h = 0; h < 4; h++) {
            float v = lacc[a][h];
#pragma unroll
            for (int m = 8; m >= 1; m >>= 1) v += __shfl_xor_sync(0xffffffffu, v, m);
            if (tx == 0) g_l[((size_t)b*S_ + i0 + 4*ty + a)*NH_ + h] = v;
        }
}

// ---------------- pass 2: weights + W@V -------------------------------------
__global__ void __launch_bounds__(256) attn_out_kernel(const float* __restrict__ v,
                                                       float* __restrict__ outp) {
    int b  = blockIdx.y;
    int i0 = blockIdx.x * 64;
    __shared__ __align__(16) float qs[64*68];   // [i][c]
    __shared__ __align__(16) float ks[32*68];   // [j][c]
    __shared__ __align__(16) float vs[64*34];   // [d][j]  pitch 34
    __shared__ __align__(16) float ws[64*36];   // [i][j]  pitch 36
    int tid = threadIdx.x;
    int tx = tid & 15, ty = tid >> 4;

    for (int fl = tid; fl < 4096; fl += 256) {
        int i = fl >> 6, c = fl & 63;
        qs[i*68 + c] = g_qp[((size_t)b*S_ + i0 + i)*C_ + c];
    }

    float linv[4][4];
#pragma unroll
    for (int a = 0; a < 4; a++)
#pragma unroll
        for (int h = 0; h < 4; h++)
            linv[a][h] = 0.25f / g_l[((size_t)b*S_ + i0 + 4*ty + a)*NH_ + h];

    ull acc2[4][4];
#pragma unroll
    for (int a = 0; a < 4; a++)
#pragma unroll
        for (int dd = 0; dd < 4; dd++) acc2[a][dd] = 0ULL;

    for (int kt = 0; kt < S_/32; kt++) {
        __syncthreads();
        for (int fl = tid; fl < 2048; fl += 256) {
            int j = fl >> 6, c = fl & 63;
            ks[j*68 + c] = g_kp[((size_t)b*S_ + kt*32 + j)*C_ + c];
        }
        for (int fl = tid; fl < 2048; fl += 256) {
            int d = fl >> 5, j = fl & 31;
            vs[d*34 + j] = v[(size_t)b*C_*S_ + (size_t)d*S_ + kt*32 + j];
        }
        __syncthreads();

        float w[4][2];
#pragma unroll
        for (int a = 0; a < 4; a++) { w[a][0] = 0.f; w[a][1] = 0.f; }
#pragma unroll
        for (int h = 0; h < 4; h++) {
            ull s2[4][2];
#pragma unroll
            for (int a = 0; a < 4; a++) { s2[a][0] = 0ULL; s2[a][1] = 0ULL; }
#pragma unroll
            for (int q4 = 0; q4 < 4; q4++) {
                int c = h*16 + q4*4;
                ulonglong2 qa[4], kb[2];
#pragma unroll
                for (int a = 0; a < 4; a++)
                    qa[a] = *(const ulonglong2*)&qs[(4*ty + a)*68 + c];
#pragma unroll
                for (int jj = 0; jj < 2; jj++)
                    kb[jj] = *(const ulonglong2*)&ks[(tx + 16*jj)*68 + c];
#pragma unroll
                for (int a = 0; a < 4; a++)
#pragma unroll
                    for (int jj = 0; jj < 2; jj++) {
                        FFMA2(s2[a][jj], qa[a].x, kb[jj].x);
                        FFMA2(s2[a][jj], qa[a].y, kb[jj].y);
                    }
            }
#pragma unroll
            for (int a = 0; a < 4; a++)
#pragma unroll
                for (int jj = 0; jj < 2; jj++)
                    w[a][jj] += __expf(hsum2(s2[a][jj])) * linv[a][h];
        }
#pragma unroll
        for (int a = 0; a < 4; a++) {
            ws[(4*ty + a)*36 + tx +  0] = w[a][0];
            ws[(4*ty + a)*36 + tx + 16] = w[a][1];
        }
        __syncthreads();

#pragma unroll
        for (int jq = 0; jq < 8; jq++) {
            ulonglong2 w2[4];
            ull va[4], vb[4];
#pragma unroll
            for (int a = 0; a < 4; a++)
                w2[a] = *(const ulonglong2*)&ws[(4*ty + a)*36 + jq*4];
#pragma unroll
            for (int dd = 0; dd < 4; dd++) {
                va[dd] = *(const ull*)&vs[(tx + 16*dd)*34 + jq*4];
                vb[dd] = *(const ull*)&vs[(tx + 16*dd)*34 + jq*4 + 2];
            }
#pragma unroll
            for (int a = 0; a < 4; a++)
#pragma unroll
                for (int dd = 0; dd < 4; dd++) {
                    FFMA2(acc2[a][dd], w2[a].x, va[dd]);
                    FFMA2(acc2[a][dd], w2[a].y, vb[dd]);
                }
        }
    }
#pragma unroll
    for (int a = 0; a < 4; a++)
#pragma unroll
        for (int dd = 0; dd < 4; dd++)
            outp[((size_t)b*S_ + i0 + 4*ty + a)*C_ + tx + 16*dd] = hsum2(acc2[a][dd]);
}

// ---------------- launch -----------------------------------------------------
extern "C" void kernel_launch(void* const* d_in, const int* in_sizes, int n_in,
                              void* d_out, int out_size) {
    const float* q      = (const float*)d_in[0];
    const float* k      = (const float*)d_in[1];
    const float* v      = (const float*)d_in[2];
    const float* conv_w = (const float*)d_in[3];
    const float* nq_w   = (const float*)d_in[4];
    const float* nk_w   = (const float*)d_in[5];
    const float* wq     = (const float*)d_in[6];
    const float* bq     = (const float*)d_in[7];
    const float* wk     = (const float*)d_in[8];
    const float* bk     = (const float*)d_in[9];
    float* outp = (float*)d_out;
    (void)in_sizes; (void)n_in; (void)out_size;

    wt_kernel<<<(C_*9*C_ + 255)/256, 256>>>(conv_w);
    conv_kernel<<<B_*H_, 256>>>(q);
    normproj_kernel<true ><<<dim3(S_/32, B_), 256>>>(nullptr, wq, nq_w, bq, 0.25f);
    normproj_kernel<false><<<dim3(S_/32, B_), 256>>>(k,       wk, nk_w, bk, 1.0f);
    attn_l_kernel  <<<dim3(S_/64, B_), 256>>>();
    attn_out_kernel<<<dim3(S_/64, B_), 256>>>(v, outp);
}

// round 6
// speedup vs baseline: 1.0200x; 1.0200x over previous
#include <cuda_runtime.h>
#include <cstdint>
#include <math.h>

#define B_  8
#define C_  64
#define H_  48
#define W_  48
#define S_  2304
#define NH_ 4
#define EPS_ 1.1920929e-07f
#define NT64 (S_/64)
#define NT32 (S_/32)

typedef unsigned long long ull;

#define FFMA2(acc, av, bv) asm("fma.rn.f32x2 %0, %1, %2, %0;" : "+l"(acc) : "l"(av), "l"(bv))

__device__ __forceinline__ float hsum2(ull v) {
    float lo, hi;
    asm("mov.b64 {%0, %1}, %2;" : "=f"(lo), "=f"(hi) : "l"(v));
    return lo + hi;
}

__device__ __forceinline__ void cp_async16(unsigned int dst, const void* src) {
    asm volatile("cp.async.ca.shared.global [%0], [%1], 16;" :: "r"(dst), "l"(src));
}
__device__ __forceinline__ void cp_commit() { asm volatile("cp.async.commit_group;"); }
template <int N>
__device__ __forceinline__ void cp_wait() { asm volatile("cp.async.wait_group %0;" :: "n"(N)); }

// ---------------- scratch ----------------------------------------------------
__device__ __align__(16) float g_wT[C_*9*C_];     // conv weights [ci*9+k][co]
__device__ __align__(16) float g_qc[B_*S_*C_];    // conv output   [b][p][c]
__device__ __align__(16) float g_qp[B_*S_*C_];    // proj q        [b][p][e]
__device__ __align__(16) float g_kp[B_*S_*C_];    // proj k        [b][p][e]
__device__ float g_l[B_*S_*NH_];                  // softmax denom [b][i][h]

// ---------------- weight transpose ------------------------------------------
__global__ void wt_kernel(const float* __restrict__ w) {
    int idx = blockIdx.x * 256 + threadIdx.x;
    if (idx >= C_*9*C_) return;
    int co = idx & 63;
    int rk = idx >> 6;
    g_wT[idx] = w[co*(C_*9) + rk];
}

// ---------------- conv 3x3 SAME, writes [b][p][c] ---------------------------
__global__ void __launch_bounds__(256) conv_kernel(const float* __restrict__ q) {
    int b = blockIdx.x / H_;
    int h = blockIdx.x % H_;
    __shared__ float in_s[3][C_][W_];
    const float* qb = q + (size_t)b*C_*H_*W_;
    for (int fl = threadIdx.x; fl < 3*C_*W_; fl += 256) {
        int r = fl / (C_*W_);
        int c = (fl / W_) % C_;
        int w = fl % W_;
        int hy = h + r - 1;
        in_s[r][c][w] = (hy >= 0 && hy < H_) ? qb[c*H_*W_ + hy*W_ + w] : 0.f;
    }
    __syncthreads();

    int co   = threadIdx.x & 63;
    int wg   = threadIdx.x >> 6;
    int base = wg * 12;

    float acc[12];
#pragma unroll
    for (int u = 0; u < 12; u++) acc[u] = 0.f;

    for (int ci = 0; ci < C_; ci++) {
#pragma unroll
        for (int r = 0; r < 3; r++) {
            float xi[14];
#pragma unroll
            for (int u = 0; u < 14; u++) {
                int x = base - 1 + u;
                xi[u] = (x >= 0 && x < W_) ? in_s[r][ci][x] : 0.f;
            }
            const float* wrow = &g_wT[(ci*9 + r*3)*C_ + co];
#pragma unroll
            for (int kw = 0; kw < 3; kw++) {
                float wv = wrow[kw*C_];
#pragma unroll
                for (int ww = 0; ww < 12; ww++) acc[ww] += xi[ww + kw] * wv;
            }
        }
    }
    float* outp = g_qc + ((size_t)b*S_ + h*W_ + base)*C_ + co;
#pragma unroll
    for (int ww = 0; ww < 12; ww++) outp[ww*C_] = acc[ww];
}

// ---------------- rmsnorm + projection (64 positions/block) -----------------
template <bool IS_Q>
__global__ void __launch_bounds__(256) normproj_kernel(
        const float* __restrict__ xin,
        const float* __restrict__ wmat,
        const float* __restrict__ nw,
        const float* __restrict__ bias,
        float scale)
{
    int b  = blockIdx.y;
    int p0 = blockIdx.x * 64;
    __shared__ __align__(16) float wm[64*68];
    __shared__ __align__(16) float xs[64*68];
    __shared__ float rinv[64];
    __shared__ float bs[64];
    int tid = threadIdx.x;

    for (int fl = tid; fl < 4096; fl += 256) {
        int e = fl >> 6, c = fl & 63;
        wm[e*68 + c] = wmat[fl] * nw[c];
    }
    if (tid < 64) bs[tid] = bias[tid];

    if (IS_Q) {
        const float4* src = (const float4*)(g_qc + ((size_t)b*S_ + p0)*C_);
        for (int fl = tid; fl < 1024; fl += 256) {
            int i = fl >> 4, c4 = fl & 15;
            float4 v = src[i*16 + c4];
            float* d = &xs[i*68 + c4*4];
            d[0] = v.x; d[1] = v.y; d[2] = v.z; d[3] = v.w;
        }
    } else {
        const float* src = xin + (size_t)b*C_*S_ + p0;
        for (int fl = tid; fl < 4096; fl += 256) {
            int c = fl >> 6, i = fl & 63;     // consecutive tid -> consecutive i (coalesced)
            xs[i*68 + c] = src[c*S_ + i];
        }
    }
    __syncthreads();

    {   // sum of squares per position (8 lanes per position, 2 rounds)
#pragma unroll
        for (int rr = 0; rr < 2; rr++) {
            int t = tid + rr*256;
            int i = t >> 3, sub = t & 7;
            float ss = 0.f;
#pragma unroll
            for (int u = 0; u < 8; u++) { float v = xs[i*68 + sub*8 + u]; ss += v*v; }
#pragma unroll
            for (int m = 4; m >= 1; m >>= 1) ss += __shfl_xor_sync(0xffffffffu, ss, m);
            if (sub == 0) rinv[i] = rsqrtf(ss * (1.f/64.f) + EPS_);
        }
    }
    __syncthreads();

    int e  = tid & 63;
    int ig = tid >> 6;   // 0..3 ; i = r*4+ig, 16 reps
    ull acc[16];
#pragma unroll
    for (int r = 0; r < 16; r++) acc[r] = 0ULL;

#pragma unroll
    for (int c = 0; c < 64; c += 4) {
        ulonglong2 w2 = *(const ulonglong2*)&wm[e*68 + c];
#pragma unroll
        for (int r = 0; r < 16; r++) {
            int i = r*4 + ig;
            ulonglong2 x2 = *(const ulonglong2*)&xs[i*68 + c];
            FFMA2(acc[r], x2.x, w2.x);
            FFMA2(acc[r], x2.y, w2.y);
        }
    }

    float* dst = (IS_Q ? g_qp : g_kp) + ((size_t)b*S_ + p0)*C_ + e;
#pragma unroll
    for (int r = 0; r < 16; r++) {
        int i = r*4 + ig;
        dst[(size_t)i*C_] = (hsum2(acc[r]) * rinv[i] + bs[e]) * scale;
    }
}

// ---------------- pass 1: per-head softmax denominators ---------------------
__global__ void __launch_bounds__(256) attn_l_kernel() {
    int b  = blockIdx.y;
    int i0 = blockIdx.x * 64;
    __shared__ __align__(16) float qs[64*68];       // [i][c]
    __shared__ __align__(16) float ks[2][64*68];    // double-buffered [j][c]
    int tid = threadIdx.x;
    int tx = tid & 15, ty = tid >> 4;

    const float* qsrc = g_qp + ((size_t)b*S_ + i0)*C_;
    for (int fl = tid; fl < 4096; fl += 256) {
        int i = fl >> 6, c = fl & 63;
        qs[i*68 + c] = qsrc[i*64 + c];
    }

    const float* kbase = g_kp + (size_t)b*S_*C_;
    unsigned int ks_sm[2];
    ks_sm[0] = (unsigned int)__cvta_generic_to_shared(&ks[0][0]);
    ks_sm[1] = (unsigned int)__cvta_generic_to_shared(&ks[1][0]);

    // prefetch tile 0
#pragma unroll
    for (int u = 0; u < 4; u++) {
        int fl = tid + u*256;                  // 1024 chunks of 16B
        int j = fl >> 4, c4 = fl & 15;
        cp_async16(ks_sm[0] + (j*68 + c4*4)*4, kbase + (size_t)j*64 + c4*4);
    }
    cp_commit();

    float lacc[4][4];
#pragma unroll
    for (int a = 0; a < 4; a++)
#pragma unroll
        for (int h = 0; h < 4; h++) lacc[a][h] = 0.f;

    for (int kt = 0; kt < NT64; kt++) {
        int cb = kt & 1, nb = cb ^ 1;
        if (kt + 1 < NT64) {
#pragma unroll
            for (int u = 0; u < 4; u++) {
                int fl = tid + u*256;
                int j = fl >> 4, c4 = fl & 15;
                cp_async16(ks_sm[nb] + (j*68 + c4*4)*4,
                           kbase + (size_t)((kt+1)*64 + j)*64 + c4*4);
            }
            cp_commit();
            cp_wait<1>();
        } else {
            cp_wait<0>();
        }
        __syncthreads();
        const float* kp = &ks[cb][0];

#pragma unroll
        for (int h = 0; h < 4; h++) {
            ull s2[4][4];
#pragma unroll
            for (int a = 0; a < 4; a++)
#pragma unroll
                for (int bb = 0; bb < 4; bb++) s2[a][bb] = 0ULL;
#pragma unroll
            for (int q4 = 0; q4 < 4; q4++) {
                int c = h*16 + q4*4;
                ulonglong2 qa[4], kb[4];
#pragma unroll
                for (int a = 0; a < 4; a++)
                    qa[a] = *(const ulonglong2*)&qs[(4*ty + a)*68 + c];
#pragma unroll
                for (int bb = 0; bb < 4; bb++)
                    kb[bb] = *(const ulonglong2*)&kp[(tx + 16*bb)*68 + c];
#pragma unroll
                for (int a = 0; a < 4; a++)
#pragma unroll
                    for (int bb = 0; bb < 4; bb++) {
                        FFMA2(s2[a][bb], qa[a].x, kb[bb].x);
                        FFMA2(s2[a][bb], qa[a].y, kb[bb].y);
                    }
            }
#pragma unroll
            for (int a = 0; a < 4; a++)
#pragma unroll
                for (int bb = 0; bb < 4; bb++)
                    lacc[a][h] += __expf(hsum2(s2[a][bb]));
        }
        __syncthreads();
    }
#pragma unroll
    for (int a = 0; a < 4; a++)
#pragma unroll
        for (int h = 0; h < 4; h++) {
            float v = lacc[a][h];
#pragma unroll
            for (int m = 8; m >= 1; m >>= 1) v += __shfl_xor_sync(0xffffffffu, v, m);
            if (tx == 0) g_l[((size_t)b*S_ + i0 + 4*ty + a)*NH_ + h] = v;
        }
}

// ---------------- pass 2: weights + W@V -------------------------------------
__global__ void __launch_bounds__(256) attn_out_kernel(const float* __restrict__ v,
                                                       float* __restrict__ outp) {
    int b  = blockIdx.y;
    int i0 = blockIdx.x * 64;
    __shared__ __align__(16) float qs[64*68];       // [i][c]
    __shared__ __align__(16) float ks[2][32*68];    // [j][c]
    __shared__ __align__(16) float vs[2][64*36];    // [d][j] pitch 36
    __shared__ __align__(16) float ws[64*36];       // [i][j] pitch 36
    int tid = threadIdx.x;
    int tx = tid & 15, ty = tid >> 4;

    const float* qsrc = g_qp + ((size_t)b*S_ + i0)*C_;
    for (int fl = tid; fl < 4096; fl += 256) {
        int i = fl >> 6, c = fl & 63;
        qs[i*68 + c] = qsrc[i*64 + c];
    }

    const float* kbase = g_kp + (size_t)b*S_*C_;
    const float* vbase = v + (size_t)b*C_*S_;
    unsigned int ks_sm[2], vs_sm[2];
    ks_sm[0] = (unsigned int)__cvta_generic_to_shared(&ks[0][0]);
    ks_sm[1] = (unsigned int)__cvta_generic_to_shared(&ks[1][0]);
    vs_sm[0] = (unsigned int)__cvta_generic_to_shared(&vs[0][0]);
    vs_sm[1] = (unsigned int)__cvta_generic_to_shared(&vs[1][0]);

    // prefetch tile 0: ks 512 chunks, vs 512 chunks
#pragma unroll
    for (int u = 0; u < 2; u++) {
        int fl = tid + u*256;
        int j = fl >> 4, c4 = fl & 15;
        cp_async16(ks_sm[0] + (j*68 + c4*4)*4, kbase + (size_t)j*64 + c4*4);
        int d = fl >> 3, j4 = fl & 7;
        cp_async16(vs_sm[0] + (d*36 + j4*4)*4, vbase + (size_t)d*S_ + j4*4);
    }
    cp_commit();

    float linv[4][4];
#pragma unroll
    for (int a = 0; a < 4; a++)
#pragma unroll
        for (int h = 0; h < 4; h++)
            linv[a][h] = 0.25f / g_l[((size_t)b*S_ + i0 + 4*ty + a)*NH_ + h];

    ull acc2[4][4];
#pragma unroll
    for (int a = 0; a < 4; a++)
#pragma unroll
        for (int dd = 0; dd < 4; dd++) acc2[a][dd] = 0ULL;

    for (int kt = 0; kt < NT32; kt++) {
        int cb = kt & 1, nb = cb ^ 1;
        if (kt + 1 < NT32) {
#pragma unroll
            for (int u = 0; u < 2; u++) {
                int fl = tid + u*256;
                int j = fl >> 4, c4 = fl & 15;
                cp_async16(ks_sm[nb] + (j*68 + c4*4)*4,
                           kbase + (size_t)((kt+1)*32 + j)*64 + c4*4);
                int d = fl >> 3, j4 = fl & 7;
                cp_async16(vs_sm[nb] + (d*36 + j4*4)*4,
                           vbase + (size_t)d*S_ + (kt+1)*32 + j4*4);
            }
            cp_commit();
            cp_wait<1>();
        } else {
            cp_wait<0>();
        }
        __syncthreads();   // buffers cb ready; ws from prev tile consumed
        const float* kp = &ks[cb][0];
        const float* vp = &vs[cb][0];

        float w[4][2];
#pragma unroll
        for (int a = 0; a < 4; a++) { w[a][0] = 0.f; w[a][1] = 0.f; }
#pragma unroll
        for (int h = 0; h < 4; h++) {
            ull s2[4][2];
#pragma unroll
            for (int a = 0; a < 4; a++) { s2[a][0] = 0ULL; s2[a][1] = 0ULL; }
#pragma unroll
            for (int q4 = 0; q4 < 4; q4++) {
                int c = h*16 + q4*4;
                ulonglong2 qa[4], kb[2];
#pragma unroll
                for (int a = 0; a < 4; a++)
                    qa[a] = *(const ulonglong2*)&qs[(4*ty + a)*68 + c];
#pragma unroll
                for (int jj = 0; jj < 2; jj++)
                    kb[jj] = *(const ulonglong2*)&kp[(tx + 16*jj)*68 + c];
#pragma unroll
                for (int a = 0; a < 4; a++)
#pragma unroll
                    for (int jj = 0; jj < 2; jj++) {
                        FFMA2(s2[a][jj], qa[a].x, kb[jj].x);
                        FFMA2(s2[a][jj], qa[a].y, kb[jj].y);
                    }
            }
#pragma unroll
            for (int a = 0; a < 4; a++)
#pragma unroll
                for (int jj = 0; jj < 2; jj++)
                    w[a][jj] += __expf(hsum2(s2[a][jj])) * linv[a][h];
        }
#pragma unroll
        for (int a = 0; a < 4; a++) {
            ws[(4*ty + a)*36 + tx +  0] = w[a][0];
            ws[(4*ty + a)*36 + tx + 16] = w[a][1];
        }
        __syncthreads();   // ws visible

#pragma unroll
        for (int jq = 0; jq < 8; jq++) {
            ulonglong2 w2[4];
            ull va[4], vb[4];
#pragma unroll
            for (int a = 0; a < 4; a++)
                w2[a] = *(const ulonglong2*)&ws[(4*ty + a)*36 + jq*4];
#pragma unroll
            for (int dd = 0; dd < 4; dd++) {
                va[dd] = *(const ull*)&vp[(tx + 16*dd)*36 + jq*4];
                vb[dd] = *(const ull*)&vp[(tx + 16*dd)*36 + jq*4 + 2];
            }
#pragma unroll
            for (int a = 0; a < 4; a++)
#pragma unroll
                for (int dd = 0; dd < 4; dd++) {
                    FFMA2(acc2[a][dd], w2[a].x, va[dd]);
                    FFMA2(acc2[a][dd], w2[a].y, vb[dd]);
                }
        }
    }
#pragma unroll
    for (int a = 0; a < 4; a++)
#pragma unroll
        for (int dd = 0; dd < 4; dd++)
            outp[((size_t)b*S_ + i0 + 4*ty + a)*C_ + tx + 16*dd] = hsum2(acc2[a][dd]);
}

// ---------------- launch -----------------------------------------------------
extern "C" void kernel_launch(void* const* d_in, const int* in_sizes, int n_in,
                              void* d_out, int out_size) {
    const float* q      = (const float*)d_in[0];
    const float* k      = (const float*)d_in[1];
    const float* v      = (const float*)d_in[2];
    const float* conv_w = (const float*)d_in[3];
    const float* nq_w   = (const float*)d_in[4];
    const float* nk_w   = (const float*)d_in[5];
    const float* wq     = (const float*)d_in[6];
    const float* bq     = (const float*)d_in[7];
    const float* wk     = (const float*)d_in[8];
    const float* bk     = (const float*)d_in[9];
    float* outp = (float*)d_out;
    (void)in_sizes; (void)n_in; (void)out_size;

    wt_kernel<<<(C_*9*C_ + 255)/256, 256>>>(conv_w);
    conv_kernel<<<B_*H_, 256>>>(q);
    normproj_kernel<true ><<<dim3(S_/64, B_), 256>>>(nullptr, wq, nq_w, bq, 0.25f);
    normproj_kernel<false><<<dim3(S_/64, B_), 256>>>(k,       wk, nk_w, bk, 1.0f);
    attn_l_kernel  <<<dim3(S_/64, B_), 256>>>();
    attn_out_kernel<<<dim3(S_/64, B_), 256>>>(v, outp);
}

// round 7
// speedup vs baseline: 1.0504x; 1.0298x over previous
#include <cuda_runtime.h>
#include <cstdint>
#include <math.h>

#define B_  8
#define C_  64
#define H_  48
#define W_  48
#define S_  2304
#define NH_ 4
#define EPS_ 1.1920929e-07f
#define NT64 (S_/64)
#define NT32 (S_/32)

typedef unsigned long long ull;

#define FFMA2(acc, av, bv) asm("fma.rn.f32x2 %0, %1, %2, %0;" : "+l"(acc) : "l"(av), "l"(bv))

__device__ __forceinline__ float hsum2(ull v) {
    float lo, hi;
    asm("mov.b64 {%0, %1}, %2;" : "=f"(lo), "=f"(hi) : "l"(v));
    return lo + hi;
}

__device__ __forceinline__ void cp_async16(unsigned int dst, const void* src) {
    asm volatile("cp.async.ca.shared.global [%0], [%1], 16;" :: "r"(dst), "l"(src));
}
__device__ __forceinline__ void cp_commit() { asm volatile("cp.async.commit_group;"); }
template <int N>
__device__ __forceinline__ void cp_wait() { asm volatile("cp.async.wait_group %0;" :: "n"(N)); }

// ---------------- scratch ----------------------------------------------------
__device__ __align__(16) float g_wT[C_*9*C_];     // conv weights [ci*9+k][co]
__device__ __align__(16) float g_qc[B_*S_*C_];    // conv output   [b][p][c]
__device__ __align__(16) float g_qp[B_*S_*C_];    // proj q        [b][p][e]
__device__ __align__(16) float g_kp[B_*S_*C_];    // proj k        [b][p][e]
__device__ float g_lp[2*B_*S_*NH_];               // softmax denom partials
__device__ __align__(16) float g_op[2*B_*S_*C_];  // output partials

// ---------------- weight transpose ------------------------------------------
__global__ void wt_kernel(const float* __restrict__ w) {
    int idx = blockIdx.x * 256 + threadIdx.x;
    if (idx >= C_*9*C_) return;
    int co = idx & 63;
    int rk = idx >> 6;
    g_wT[idx] = w[co*(C_*9) + rk];
}

// ---------------- conv 3x3 SAME, writes [b][p][c] ---------------------------
__global__ void __launch_bounds__(256) conv_kernel(const float* __restrict__ q) {
    int b = blockIdx.x / H_;
    int h = blockIdx.x % H_;
    __shared__ float in_s[3][C_][W_];
    const float* qb = q + (size_t)b*C_*H_*W_;
    for (int fl = threadIdx.x; fl < 3*C_*W_; fl += 256) {
        int r = fl / (C_*W_);
        int c = (fl / W_) % C_;
        int w = fl % W_;
        int hy = h + r - 1;
        in_s[r][c][w] = (hy >= 0 && hy < H_) ? qb[c*H_*W_ + hy*W_ + w] : 0.f;
    }
    __syncthreads();

    int co   = threadIdx.x & 63;
    int wg   = threadIdx.x >> 6;
    int base = wg * 12;

    float acc[12];
#pragma unroll
    for (int u = 0; u < 12; u++) acc[u] = 0.f;

    for (int ci = 0; ci < C_; ci++) {
#pragma unroll
        for (int r = 0; r < 3; r++) {
            float xi[14];
#pragma unroll
            for (int u = 0; u < 14; u++) {
                int x = base - 1 + u;
                xi[u] = (x >= 0 && x < W_) ? in_s[r][ci][x] : 0.f;
            }
            const float* wrow = &g_wT[(ci*9 + r*3)*C_ + co];
#pragma unroll
            for (int kw = 0; kw < 3; kw++) {
                float wv = wrow[kw*C_];
#pragma unroll
                for (int ww = 0; ww < 12; ww++) acc[ww] += xi[ww + kw] * wv;
            }
        }
    }
    float* outp = g_qc + ((size_t)b*S_ + h*W_ + base)*C_ + co;
#pragma unroll
    for (int ww = 0; ww < 12; ww++) outp[ww*C_] = acc[ww];
}

// ---------------- rmsnorm + projection (64 positions/block) -----------------
template <bool IS_Q>
__global__ void __launch_bounds__(256) normproj_kernel(
        const float* __restrict__ xin,
        const float* __restrict__ wmat,
        const float* __restrict__ nw,
        const float* __restrict__ bias,
        float scale)
{
    int b  = blockIdx.y;
    int p0 = blockIdx.x * 64;
    __shared__ __align__(16) float wm[64*68];
    __shared__ __align__(16) float xs[64*68];
    __shared__ float rinv[64];
    __shared__ float bs[64];
    int tid = threadIdx.x;

    for (int fl = tid; fl < 4096; fl += 256) {
        int e = fl >> 6, c = fl & 63;
        wm[e*68 + c] = wmat[fl] * nw[c];
    }
    if (tid < 64) bs[tid] = bias[tid];

    if (IS_Q) {
        const float4* src = (const float4*)(g_qc + ((size_t)b*S_ + p0)*C_);
        for (int fl = tid; fl < 1024; fl += 256) {
            int i = fl >> 4, c4 = fl & 15;
            float4 v = src[i*16 + c4];
            float* d = &xs[i*68 + c4*4];
            d[0] = v.x; d[1] = v.y; d[2] = v.z; d[3] = v.w;
        }
    } else {
        const float* src = xin + (size_t)b*C_*S_ + p0;
        for (int fl = tid; fl < 4096; fl += 256) {
            int c = fl >> 6, i = fl & 63;
            xs[i*68 + c] = src[c*S_ + i];
        }
    }
    __syncthreads();

    {
#pragma unroll
        for (int rr = 0; rr < 2; rr++) {
            int t = tid + rr*256;
            int i = t >> 3, sub = t & 7;
            float ss = 0.f;
#pragma unroll
            for (int u = 0; u < 8; u++) { float v = xs[i*68 + sub*8 + u]; ss += v*v; }
#pragma unroll
            for (int m = 4; m >= 1; m >>= 1) ss += __shfl_xor_sync(0xffffffffu, ss, m);
            if (sub == 0) rinv[i] = rsqrtf(ss * (1.f/64.f) + EPS_);
        }
    }
    __syncthreads();

    int e  = tid & 63;
    int ig = tid >> 6;
    ull acc[16];
#pragma unroll
    for (int r = 0; r < 16; r++) acc[r] = 0ULL;

#pragma unroll
    for (int c = 0; c < 64; c += 4) {
        ulonglong2 w2 = *(const ulonglong2*)&wm[e*68 + c];
#pragma unroll
        for (int r = 0; r < 16; r++) {
            int i = r*4 + ig;
            ulonglong2 x2 = *(const ulonglong2*)&xs[i*68 + c];
            FFMA2(acc[r], x2.x, w2.x);
            FFMA2(acc[r], x2.y, w2.y);
        }
    }

    float* dst = (IS_Q ? g_qp : g_kp) + ((size_t)b*S_ + p0)*C_ + e;
#pragma unroll
    for (int r = 0; r < 16; r++) {
        int i = r*4 + ig;
        dst[(size_t)i*C_] = (hsum2(acc[r]) * rinv[i] + bs[e]) * scale;
    }
}

// ---------------- pass 1: per-head softmax denominators ---------------------
// grid: (S/64, NH*2, B)  -- one head + one j-half per block; q in registers
__global__ void __launch_bounds__(256) attn_l_kernel() {
    int b    = blockIdx.z;
    int h    = blockIdx.y >> 1;
    int half = blockIdx.y & 1;
    int i0   = blockIdx.x * 64;
    __shared__ __align__(16) float qsh[64*20];     // [i][16c] pitch 20
    __shared__ __align__(16) float ks[2][64*36];   // [j][16c] pitch 36
    int tid = threadIdx.x;
    int tx = tid & 15, ty = tid >> 4;

    // load q head-slice: 64 rows x 16 c (float4 per thread)
    {
        int i = tid >> 2, c4 = tid & 3;
        const float4* src = (const float4*)(g_qp + ((size_t)b*S_ + i0 + i)*C_ + h*16);
        *(float4*)&qsh[i*20 + c4*4] = src[c4];
    }

    const float* kbase = g_kp + (size_t)b*S_*C_ + h*16;
    unsigned int ks_sm[2];
    ks_sm[0] = (unsigned int)__cvta_generic_to_shared(&ks[0][0]);
    ks_sm[1] = (unsigned int)__cvta_generic_to_shared(&ks[1][0]);

    const int kt0 = half * (NT64/2);    // 18 tiles per half
    {   // prefetch first k slice: 256 chunks of 16B
        int j = tid >> 2, c4 = tid & 3;
        cp_async16(ks_sm[0] + (j*36 + c4*4)*4, kbase + (size_t)(kt0*64 + j)*64 + c4*4);
    }
    cp_commit();
    __syncthreads();

    // q fragment in registers: 4 rows x 16 c
    ulonglong2 qf[4][4];
#pragma unroll
    for (int a = 0; a < 4; a++)
#pragma unroll
        for (int q4 = 0; q4 < 4; q4++)
            qf[a][q4] = *(const ulonglong2*)&qsh[(4*ty + a)*20 + q4*4];

    float lacc[4] = {0.f, 0.f, 0.f, 0.f};

    for (int t = 0; t < NT64/2; t++) {
        int cb = t & 1, nb = cb ^ 1;
        if (t + 1 < NT64/2) {
            int j = tid >> 2, c4 = tid & 3;
            cp_async16(ks_sm[nb] + (j*36 + c4*4)*4,
                       kbase + (size_t)((kt0 + t + 1)*64 + j)*64 + c4*4);
            cp_commit();
            cp_wait<1>();
        } else {
            cp_wait<0>();
        }
        __syncthreads();
        const float* kp = &ks[cb][0];

        ull s2[4][4];
#pragma unroll
        for (int a = 0; a < 4; a++)
#pragma unroll
            for (int bb = 0; bb < 4; bb++) s2[a][bb] = 0ULL;
#pragma unroll
        for (int q4 = 0; q4 < 4; q4++) {
            ulonglong2 kb[4];
#pragma unroll
            for (int bb = 0; bb < 4; bb++)
                kb[bb] = *(const ulonglong2*)&kp[(tx + 16*bb)*36 + q4*4];
#pragma unroll
            for (int a = 0; a < 4; a++)
#pragma unroll
                for (int bb = 0; bb < 4; bb++) {
                    FFMA2(s2[a][bb], qf[a][q4].x, kb[bb].x);
                    FFMA2(s2[a][bb], qf[a][q4].y, kb[bb].y);
                }
        }
#pragma unroll
        for (int a = 0; a < 4; a++)
#pragma unroll
            for (int bb = 0; bb < 4; bb++)
                lacc[a] += __expf(hsum2(s2[a][bb]));
        __syncthreads();
    }

#pragma unroll
    for (int a = 0; a < 4; a++) {
        float v = lacc[a];
#pragma unroll
        for (int m = 8; m >= 1; m >>= 1) v += __shfl_xor_sync(0xffffffffu, v, m);
        if (tx == 0)
            g_lp[(size_t)half*B_*S_*NH_ + ((size_t)b*S_ + i0 + 4*ty + a)*NH_ + h] = v;
    }
}

// ---------------- pass 2: weights + W@V (j-split 2) --------------------------
__global__ void __launch_bounds__(256) attn_out_kernel(const float* __restrict__ v) {
    int b    = blockIdx.z;
    int half = blockIdx.y;
    int i0   = blockIdx.x * 64;
    __shared__ __align__(16) float qs[64*68];       // [i][c]
    __shared__ __align__(16) float ks[2][32*68];    // [j][c]
    __shared__ __align__(16) float vs[2][64*36];    // [d][j] pitch 36
    __shared__ __align__(16) float ws[64*36];       // [i][j] pitch 36
    int tid = threadIdx.x;
    int tx = tid & 15, ty = tid >> 4;

    const float* qsrc = g_qp + ((size_t)b*S_ + i0)*C_;
    for (int fl = tid; fl < 4096; fl += 256) {
        int i = fl >> 6, c = fl & 63;
        qs[i*68 + c] = qsrc[i*64 + c];
    }

    const float* kbase = g_kp + (size_t)b*S_*C_;
    const float* vbase = v + (size_t)b*C_*S_;
    unsigned int ks_sm[2], vs_sm[2];
    ks_sm[0] = (unsigned int)__cvta_generic_to_shared(&ks[0][0]);
    ks_sm[1] = (unsigned int)__cvta_generic_to_shared(&ks[1][0]);
    vs_sm[0] = (unsigned int)__cvta_generic_to_shared(&vs[0][0]);
    vs_sm[1] = (unsigned int)__cvta_generic_to_shared(&vs[1][0]);

    const int kt0 = half * (NT32/2);   // 36 tiles per half

    // prefetch tile kt0
#pragma unroll
    for (int u = 0; u < 2; u++) {
        int fl = tid + u*256;
        int j = fl >> 4, c4 = fl & 15;
        cp_async16(ks_sm[0] + (j*68 + c4*4)*4, kbase + (size_t)(kt0*32 + j)*64 + c4*4);
        int d = fl >> 3, j4 = fl & 7;
        cp_async16(vs_sm[0] + (d*36 + j4*4)*4, vbase + (size_t)d*S_ + kt0*32 + j4*4);
    }
    cp_commit();

    float linv[4][4];
#pragma unroll
    for (int a = 0; a < 4; a++)
#pragma unroll
        for (int h = 0; h < 4; h++) {
            size_t li = ((size_t)b*S_ + i0 + 4*ty + a)*NH_ + h;
            linv[a][h] = 0.25f / (g_lp[li] + g_lp[(size_t)B_*S_*NH_ + li]);
        }

    ull acc2[4][4];
#pragma unroll
    for (int a = 0; a < 4; a++)
#pragma unroll
        for (int dd = 0; dd < 4; dd++) acc2[a][dd] = 0ULL;

    for (int t = 0; t < NT32/2; t++) {
        int cb = t & 1, nb = cb ^ 1;
        if (t + 1 < NT32/2) {
#pragma unroll
            for (int u = 0; u < 2; u++) {
                int fl = tid + u*256;
                int j = fl >> 4, c4 = fl & 15;
                cp_async16(ks_sm[nb] + (j*68 + c4*4)*4,
                           kbase + (size_t)((kt0 + t + 1)*32 + j)*64 + c4*4);
                int d = fl >> 3, j4 = fl & 7;
                cp_async16(vs_sm[nb] + (d*36 + j4*4)*4,
                           vbase + (size_t)d*S_ + (kt0 + t + 1)*32 + j4*4);
            }
            cp_commit();
            cp_wait<1>();
        } else {
            cp_wait<0>();
        }
        __syncthreads();
        const float* kp = &ks[cb][0];
        const float* vp = &vs[cb][0];

        float w[4][2];
#pragma unroll
        for (int a = 0; a < 4; a++) { w[a][0] = 0.f; w[a][1] = 0.f; }
#pragma unroll
        for (int h = 0; h < 4; h++) {
            ull s2[4][2];
#pragma unroll
            for (int a = 0; a < 4; a++) { s2[a][0] = 0ULL; s2[a][1] = 0ULL; }
#pragma unroll
            for (int q4 = 0; q4 < 4; q4++) {
                int c = h*16 + q4*4;
                ulonglong2 qa[4], kb[2];
#pragma unroll
                for (int a = 0; a < 4; a++)
                    qa[a] = *(const ulonglong2*)&qs[(4*ty + a)*68 + c];
#pragma unroll
                for (int jj = 0; jj < 2; jj++)
                    kb[jj] = *(const ulonglong2*)&kp[(tx + 16*jj)*68 + c];
#pragma unroll
                for (int a = 0; a < 4; a++)
#pragma unroll
                    for (int jj = 0; jj < 2; jj++) {
                        FFMA2(s2[a][jj], qa[a].x, kb[jj].x);
                        FFMA2(s2[a][jj], qa[a].y, kb[jj].y);
                    }
            }
#pragma unroll
            for (int a = 0; a < 4; a++)
#pragma unroll
                for (int jj = 0; jj < 2; jj++)
                    w[a][jj] += __expf(hsum2(s2[a][jj])) * linv[a][h];
        }
#pragma unroll
        for (int a = 0; a < 4; a++) {
            ws[(4*ty + a)*36 + tx +  0] = w[a][0];
            ws[(4*ty + a)*36 + tx + 16] = w[a][1];
        }
        __syncthreads();

#pragma unroll
        for (int jq = 0; jq < 8; jq++) {
            ulonglong2 w2[4];
            ull va[4], vb[4];
#pragma unroll
            for (int a = 0; a < 4; a++)
                w2[a] = *(const ulonglong2*)&ws[(4*ty + a)*36 + jq*4];
#pragma unroll
            for (int dd = 0; dd < 4; dd++) {
                va[dd] = *(const ull*)&vp[(tx + 16*dd)*36 + jq*4];
                vb[dd] = *(const ull*)&vp[(tx + 16*dd)*36 + jq*4 + 2];
            }
#pragma unroll
            for (int a = 0; a < 4; a++)
#pragma unroll
                for (int dd = 0; dd < 4; dd++) {
                    FFMA2(acc2[a][dd], w2[a].x, va[dd]);
                    FFMA2(acc2[a][dd], w2[a].y, vb[dd]);
                }
        }
    }
    float* op = g_op + (size_t)half*B_*S_*C_;
#pragma unroll
    for (int a = 0; a < 4; a++)
#pragma unroll
        for (int dd = 0; dd < 4; dd++)
            op[((size_t)b*S_ + i0 + 4*ty + a)*C_ + tx + 16*dd] = hsum2(acc2[a][dd]);
}

// ---------------- combine halves ---------------------------------------------
__global__ void combine_kernel(float* __restrict__ outp) {
    int idx = blockIdx.x * 256 + threadIdx.x;     // float4 index
    const int n4 = B_*S_*C_/4;
    if (idx >= n4) return;
    float4 a = ((const float4*)g_op)[idx];
    float4 b = ((const float4*)g_op)[n4 + idx];
    ((float4*)outp)[idx] = make_float4(a.x + b.x, a.y + b.y, a.z + b.z, a.w + b.w);
}

// ---------------- launch -----------------------------------------------------
extern "C" void kernel_launch(void* const* d_in, const int* in_sizes, int n_in,
                              void* d_out, int out_size) {
    const float* q      = (const float*)d_in[0];
    const float* k      = (const float*)d_in[1];
    const float* v      = (const float*)d_in[2];
    const float* conv_w = (const float*)d_in[3];
    const float* nq_w   = (const float*)d_in[4];
    const float* nk_w   = (const float*)d_in[5];
    const float* wq     = (const float*)d_in[6];
    const float* bq     = (const float*)d_in[7];
    const float* wk     = (const float*)d_in[8];
    const float* bk     = (const float*)d_in[9];
    float* outp = (float*)d_out;
    (void)in_sizes; (void)n_in; (void)out_size;

    wt_kernel<<<(C_*9*C_ + 255)/256, 256>>>(conv_w);
    conv_kernel<<<B_*H_, 256>>>(q);
    normproj_kernel<true ><<<dim3(S_/64, B_), 256>>>(nullptr, wq, nq_w, bq, 0.25f);
    normproj_kernel<false><<<dim3(S_/64, B_), 256>>>(k,       wk, nk_w, bk, 1.0f);
    attn_l_kernel  <<<dim3(S_/64, NH_*2, B_), 256>>>();
    attn_out_kernel<<<dim3(S_/64, 2, B_), 256>>>(v);
    combine_kernel <<<(B_*S_*C_/4 + 255)/256, 256>>>(outp);
}